// round 1
// baseline (speedup 1.0000x reference)
#include <cuda_runtime.h>
#include <math.h>

#define NN 4096
#define DD 256

// ---------------- scratch (device globals; no allocation allowed) ----------------
__device__ float g_spa_emb[NN * DD];
__device__ float g_tmp_emb[NN * DD];
__device__ float g_node_fea[NN * DD];
__device__ float g_spa_fea[NN * DD];
__device__ float g_tmp_fea[NN * DD];
__device__ float g_val[NN * DD];
__device__ float g_deg_s[NN];
__device__ float g_deg_t[NN];
__device__ float g_rowabs_s[NN];
__device__ float g_rowsq_s[NN];
__device__ float g_rowabs_t[NN];
__device__ float g_rowsq_t[NN];
__device__ float g_sqpart_s[256];
__device__ float g_sqpart_t[256];

// ---------------- helpers ----------------
__device__ __forceinline__ float block_sum_256(float v, float* red) {
    int t = threadIdx.x;
    red[t] = v;
    __syncthreads();
#pragma unroll
    for (int s = 128; s > 0; s >>= 1) {
        if (t < s) red[t] += red[t + s];
        __syncthreads();
    }
    float r = red[0];
    __syncthreads();
    return r;
}

// ---------------- K1/K2: per-row |x|, x^2, relu-sum (degree) ----------------
__global__ __launch_bounds__(256) void row_reduce_kernel(
    const float* __restrict__ inc, int L,
    float* __restrict__ rowabs, float* __restrict__ rowsq, float* __restrict__ deg)
{
    __shared__ float red[256];
    int i = blockIdx.x;
    const float* row = inc + (size_t)i * L;
    float sa = 0.f, ss = 0.f, sd = 0.f;
    for (int j = threadIdx.x; j < L; j += 256) {
        float v = __ldg(&row[j]);
        sa += fabsf(v);
        ss += v * v;
        sd += fmaxf(v, 0.f);
    }
    sa = block_sum_256(sa, red);
    ss = block_sum_256(ss, red);
    sd = block_sum_256(sd, red);
    if (threadIdx.x == 0) {
        rowabs[i] = sa;
        rowsq[i]  = ss;
        deg[i]    = sd + 1.0f;
    }
}

// ---------------- K3/K4: fused incidence GEMM ----------------
// Computes (per 64x64 output tile):
//   recon  = M @ mainX            (M = scattered incidence, raw)
//   racc   = relu(M) @ mainX
//   master = cur @ rproj          (extra K=256 pass)
//   emb    = (racc + cur) / deg   (written out)
//   sqpart = sum((master - recon)^2) per block (for the fro loss)
template<bool SPATIAL>
__global__ __launch_bounds__(256, 2) void fused_inc_kernel(
    const float* __restrict__ inc,
    const float* __restrict__ mainX,
    const float* __restrict__ cur,
    const float* __restrict__ rproj,
    const float* __restrict__ deg,
    float* __restrict__ emb,
    float* __restrict__ sqpart)
{
    const int row0 = blockIdx.y * 64;
    const int col0 = blockIdx.x * 64;
    const int tid = threadIdx.x;
    const int ty = tid >> 4, tx = tid & 15;

    __shared__ float As[16][64];
    __shared__ float Bs[16][64];
    __shared__ float red[256];

    float acc1[4][4]; // raw (recon)
    float acc2[4][4]; // relu
#pragma unroll
    for (int m = 0; m < 4; m++)
#pragma unroll
        for (int n = 0; n < 4; n++) { acc1[m][n] = 0.f; acc2[m][n] = 0.f; }

    const int lr = tid >> 2;          // 0..63 (A row within tile)
    const int lk = (tid & 3) * 4;     // 0,4,8,12 (A k group)
    const int bk = tid >> 4;          // 0..15   (B k row)
    const int bn = (tid & 15) * 4;    // B col group
    const int i_glob = row0 + lr;

    for (int k0 = 0; k0 < NN; k0 += 16) {
#pragma unroll
        for (int c = 0; c < 4; c++) {
            int j = k0 + lk + c;
            float v;
            if (SPATIAL) {
                v = (j == i_glob) ? 0.f
                    : __ldg(&inc[i_glob * (NN - 1) + (j < i_glob ? j : j - 1)]);
            } else {
                v = __ldg(&inc[(size_t)i_glob * NN + j]);
            }
            As[lk + c][lr] = v;
        }
        *(float4*)&Bs[bk][bn] =
            *(const float4*)&mainX[(size_t)(k0 + bk) * DD + col0 + bn];
        __syncthreads();
#pragma unroll
        for (int k = 0; k < 16; k++) {
            float4 a4 = *(const float4*)&As[k][ty * 4];
            float4 b4 = *(const float4*)&Bs[k][tx * 4];
            float am[4] = {a4.x, a4.y, a4.z, a4.w};
            float ar[4] = {fmaxf(a4.x, 0.f), fmaxf(a4.y, 0.f),
                           fmaxf(a4.z, 0.f), fmaxf(a4.w, 0.f)};
            float bv[4] = {b4.x, b4.y, b4.z, b4.w};
#pragma unroll
            for (int m = 0; m < 4; m++)
#pragma unroll
                for (int n = 0; n < 4; n++) {
                    acc1[m][n] = fmaf(am[m], bv[n], acc1[m][n]);
                    acc2[m][n] = fmaf(ar[m], bv[n], acc2[m][n]);
                }
        }
        __syncthreads();
    }

    // acc1 := master - recon  (negate, then accumulate master)
#pragma unroll
    for (int m = 0; m < 4; m++)
#pragma unroll
        for (int n = 0; n < 4; n++) acc1[m][n] = -acc1[m][n];

    for (int k0 = 0; k0 < DD; k0 += 16) {
        float4 a4 = *(const float4*)&cur[(size_t)(row0 + lr) * DD + k0 + lk];
        As[lk + 0][lr] = a4.x; As[lk + 1][lr] = a4.y;
        As[lk + 2][lr] = a4.z; As[lk + 3][lr] = a4.w;
        *(float4*)&Bs[bk][bn] =
            *(const float4*)&rproj[(size_t)(k0 + bk) * DD + col0 + bn];
        __syncthreads();
#pragma unroll
        for (int k = 0; k < 16; k++) {
            float4 a = *(const float4*)&As[k][ty * 4];
            float4 b = *(const float4*)&Bs[k][tx * 4];
            float am[4] = {a.x, a.y, a.z, a.w};
            float bv[4] = {b.x, b.y, b.z, b.w};
#pragma unroll
            for (int m = 0; m < 4; m++)
#pragma unroll
                for (int n = 0; n < 4; n++)
                    acc1[m][n] = fmaf(am[m], bv[n], acc1[m][n]);
        }
        __syncthreads();
    }

    float sq = 0.f;
#pragma unroll
    for (int m = 0; m < 4; m++) {
        int gi = row0 + ty * 4 + m;
        float invd = 1.0f / __ldg(&deg[gi]);
        float4 c4 = *(const float4*)&cur[(size_t)gi * DD + col0 + tx * 4];
        float cv[4] = {c4.x, c4.y, c4.z, c4.w};
#pragma unroll
        for (int n = 0; n < 4; n++) {
            float d = acc1[m][n];
            sq = fmaf(d, d, sq);
        }
        float4 o;
        o.x = (acc2[m][0] + cv[0]) * invd;
        o.y = (acc2[m][1] + cv[1]) * invd;
        o.z = (acc2[m][2] + cv[2]) * invd;
        o.w = (acc2[m][3] + cv[3]) * invd;
        *(float4*)&emb[(size_t)gi * DD + col0 + tx * 4] = o;
    }

    float s = block_sum_256(sq, red);
    if (tid == 0) sqpart[blockIdx.y * gridDim.x + blockIdx.x] = s;
}

// ---------------- K5/K7: small GEMM C = A[N,D] @ op(B[D,D]) (+bias, relu) ----------------
template<bool TRANSB, bool RELUBIAS>
__global__ __launch_bounds__(256, 2) void gemm256_kernel(
    const float* __restrict__ A, const float* __restrict__ B,
    const float* __restrict__ bias, float* __restrict__ C)
{
    const int row0 = blockIdx.y * 64;
    const int col0 = blockIdx.x * 64;
    const int tid = threadIdx.x;
    const int ty = tid >> 4, tx = tid & 15;

    __shared__ float As[16][64];
    __shared__ float Bs[16][64];

    float acc[4][4];
#pragma unroll
    for (int m = 0; m < 4; m++)
#pragma unroll
        for (int n = 0; n < 4; n++) acc[m][n] = 0.f;

    const int lr = tid >> 2, lk = (tid & 3) * 4;
    const int bk = tid >> 4, bn = (tid & 15) * 4;
    const int tn = tid >> 2, tkq = (tid & 3) * 4;

    for (int k0 = 0; k0 < DD; k0 += 16) {
        float4 a4 = *(const float4*)&A[(size_t)(row0 + lr) * DD + k0 + lk];
        As[lk + 0][lr] = a4.x; As[lk + 1][lr] = a4.y;
        As[lk + 2][lr] = a4.z; As[lk + 3][lr] = a4.w;
        if (!TRANSB) {
            *(float4*)&Bs[bk][bn] =
                *(const float4*)&B[(size_t)(k0 + bk) * DD + col0 + bn];
        } else {
            float4 w = *(const float4*)&B[(size_t)(col0 + tn) * DD + k0 + tkq];
            Bs[tkq + 0][tn] = w.x; Bs[tkq + 1][tn] = w.y;
            Bs[tkq + 2][tn] = w.z; Bs[tkq + 3][tn] = w.w;
        }
        __syncthreads();
#pragma unroll
        for (int k = 0; k < 16; k++) {
            float4 a = *(const float4*)&As[k][ty * 4];
            float4 b = *(const float4*)&Bs[k][tx * 4];
            float am[4] = {a.x, a.y, a.z, a.w};
            float bv[4] = {b.x, b.y, b.z, b.w};
#pragma unroll
            for (int m = 0; m < 4; m++)
#pragma unroll
                for (int n = 0; n < 4; n++)
                    acc[m][n] = fmaf(am[m], bv[n], acc[m][n]);
        }
        __syncthreads();
    }

#pragma unroll
    for (int m = 0; m < 4; m++) {
        int gi = row0 + ty * 4 + m;
        float4 o;
        float v0 = acc[m][0], v1 = acc[m][1], v2 = acc[m][2], v3 = acc[m][3];
        if (RELUBIAS) {
            int gj = col0 + tx * 4;
            v0 = fmaxf(v0 + __ldg(&bias[gj + 0]), 0.f);
            v1 = fmaxf(v1 + __ldg(&bias[gj + 1]), 0.f);
            v2 = fmaxf(v2 + __ldg(&bias[gj + 2]), 0.f);
            v3 = fmaxf(v3 + __ldg(&bias[gj + 3]), 0.f);
        }
        o.x = v0; o.y = v1; o.z = v2; o.w = v3;
        *(float4*)&C[(size_t)gi * DD + col0 + tx * 4] = o;
    }
}

// ---------------- K6: attention + val ----------------
__global__ __launch_bounds__(256) void attn_val_kernel() {
    __shared__ float red[256];
    int i = blockIdx.x;
    int d = threadIdx.x;
    size_t idx = (size_t)i * DD + d;
    float nf = g_node_fea[idx];
    float sf = g_spa_fea[idx];
    float tf = g_tmp_fea[idx];
    float ds = block_sum_256(sf * nf, red);
    float dt = block_sum_256(tf * nf, red);
    float as = ds * 0.0625f;  // 1/sqrt(256)
    float at = dt * 0.0625f;
    g_val[idx] = as * sf + at * tf;
}

// ---------------- K8: finalize loss ----------------
__global__ __launch_bounds__(256) void finalize_kernel(float* __restrict__ out, int out_size) {
    __shared__ float red[256];
    int t = threadIdx.x;
    float abs_s = 0.f, sq_s = 0.f, abs_t = 0.f, sq_t = 0.f;
    for (int i = t; i < NN; i += 256) {
        abs_s += g_rowabs_s[i];
        sq_s  += g_rowsq_s[i];
        abs_t += g_rowabs_t[i];
        sq_t  += g_rowsq_t[i];
    }
    float d_s = g_sqpart_s[t];
    float d_t = g_sqpart_t[t];
    abs_s = block_sum_256(abs_s, red);
    sq_s  = block_sum_256(sq_s,  red);
    abs_t = block_sum_256(abs_t, red);
    sq_t  = block_sum_256(sq_t,  red);
    d_s   = block_sum_256(d_s,   red);
    d_t   = block_sum_256(d_t,   red);
    float loss = 0.2f * sqrtf(d_s) + abs_s + 0.001f * sqrtf(sq_s)
               + 0.2f * sqrtf(d_t) + abs_t + 0.001f * sqrtf(sq_t);
    for (int idx = NN * DD + t; idx < out_size; idx += 256)
        out[idx] = loss;
}

// ---------------- launch ----------------
extern "C" void kernel_launch(void* const* d_in, const int* in_sizes, int n_in,
                              void* d_out, int out_size) {
    const float* cur           = (const float*)d_in[0];
    const float* pre           = (const float*)d_in[1];
    const float* r_proj_s      = (const float*)d_in[2];
    const float* inc_s         = (const float*)d_in[3];
    const float* r_proj_t      = (const float*)d_in[4];
    const float* inc_t         = (const float*)d_in[5];
    const float* node_proj     = (const float*)d_in[6];
    const float* spa_edge_proj = (const float*)d_in[7];
    const float* tmp_edge_proj = (const float*)d_in[8];
    const float* theta_w       = (const float*)d_in[9];
    const float* theta_b       = (const float*)d_in[10];
    float* out = (float*)d_out;

    float *p_spa_emb, *p_tmp_emb, *p_node_fea, *p_spa_fea, *p_tmp_fea, *p_val;
    float *p_deg_s, *p_deg_t, *p_rowabs_s, *p_rowsq_s, *p_rowabs_t, *p_rowsq_t;
    float *p_sqpart_s, *p_sqpart_t;
    cudaGetSymbolAddress((void**)&p_spa_emb,  g_spa_emb);
    cudaGetSymbolAddress((void**)&p_tmp_emb,  g_tmp_emb);
    cudaGetSymbolAddress((void**)&p_node_fea, g_node_fea);
    cudaGetSymbolAddress((void**)&p_spa_fea,  g_spa_fea);
    cudaGetSymbolAddress((void**)&p_tmp_fea,  g_tmp_fea);
    cudaGetSymbolAddress((void**)&p_val,      g_val);
    cudaGetSymbolAddress((void**)&p_deg_s,    g_deg_s);
    cudaGetSymbolAddress((void**)&p_deg_t,    g_deg_t);
    cudaGetSymbolAddress((void**)&p_rowabs_s, g_rowabs_s);
    cudaGetSymbolAddress((void**)&p_rowsq_s,  g_rowsq_s);
    cudaGetSymbolAddress((void**)&p_rowabs_t, g_rowabs_t);
    cudaGetSymbolAddress((void**)&p_rowsq_t,  g_rowsq_t);
    cudaGetSymbolAddress((void**)&p_sqpart_s, g_sqpart_s);
    cudaGetSymbolAddress((void**)&p_sqpart_t, g_sqpart_t);

    // K1/K2: row reductions (degrees + loss row sums)
    row_reduce_kernel<<<NN, 256>>>(inc_s, NN - 1, p_rowabs_s, p_rowsq_s, p_deg_s);
    row_reduce_kernel<<<NN, 256>>>(inc_t, NN,     p_rowabs_t, p_rowsq_t, p_deg_t);

    dim3 grid(DD / 64, NN / 64); // (4, 64) = 256 blocks

    // K3: spatial fused (M = scatter(inc_s), X = cur, add cur, proj r_proj_s)
    fused_inc_kernel<true><<<grid, 256>>>(inc_s, cur, cur, r_proj_s,
                                          p_deg_s, p_spa_emb, p_sqpart_s);
    // K4: temporal fused (M = inc_t, X = pre, add cur, proj r_proj_t)
    fused_inc_kernel<false><<<grid, 256>>>(inc_t, pre, cur, r_proj_t,
                                           p_deg_t, p_tmp_emb, p_sqpart_t);

    // K5: feature projections
    gemm256_kernel<false, false><<<grid, 256>>>(cur,       node_proj,     nullptr, p_node_fea);
    gemm256_kernel<false, false><<<grid, 256>>>(p_spa_emb, spa_edge_proj, nullptr, p_spa_fea);
    gemm256_kernel<false, false><<<grid, 256>>>(p_tmp_emb, tmp_edge_proj, nullptr, p_tmp_fea);

    // K6: attention + val
    attn_val_kernel<<<NN, 256>>>();

    // K7: node_emb = relu(val @ theta_w^T + theta_b)  -> d_out[0 .. N*D)
    gemm256_kernel<true, true><<<grid, 256>>>(p_val, theta_w, theta_b, out);

    // K8: loss scalar -> d_out[N*D ...]
    finalize_kernel<<<1, 256>>>(out, out_size);
}

// round 4
// speedup vs baseline: 2.6545x; 2.6545x over previous
#include <cuda_runtime.h>
#include <cuda_bf16.h>
#include <math.h>
#include <stdint.h>

#define NN 4096
#define DD 256

// ---------------- scratch (device globals; no allocation allowed) ----------------
__device__ float g_spa_emb[NN * DD];
__device__ float g_tmp_emb[NN * DD];
__device__ float g_node_fea[NN * DD];
__device__ float g_spa_fea[NN * DD];
__device__ float g_tmp_fea[NN * DD];
__device__ float g_val[NN * DD];
__device__ float g_master_s[NN * DD];
__device__ float g_master_t[NN * DD];
__device__ float g_deg_s[NN];
__device__ float g_deg_t[NN];
__device__ float g_rowabs_s[NN];
__device__ float g_rowsq_s[NN];
__device__ float g_rowabs_t[NN];
__device__ float g_rowsq_t[NN];
__device__ float g_sqpart_s[64];
__device__ float g_sqpart_t[64];
// pre-split, pre-transposed X: [D][N] bf16 hi/lo
__device__ __nv_bfloat16 g_bhi_s[DD * NN];
__device__ __nv_bfloat16 g_blo_s[DD * NN];
__device__ __nv_bfloat16 g_bhi_t[DD * NN];
__device__ __nv_bfloat16 g_blo_t[DD * NN];

// ---------------- PTX helpers (sm_80-baseline only) ----------------
__device__ __forceinline__ uint32_t smem_to_u32(const void* p) {
    uint32_t a;
    asm("{ .reg .u64 t; cvta.to.shared.u64 t, %1; cvt.u32.u64 %0, t; }" : "=r"(a) : "l"(p));
    return a;
}

__device__ __forceinline__ void ldsm4(uint32_t& r0, uint32_t& r1, uint32_t& r2, uint32_t& r3,
                                      uint32_t addr) {
    asm volatile("ldmatrix.sync.aligned.m8n8.x4.shared.b16 {%0,%1,%2,%3}, [%4];"
                 : "=r"(r0), "=r"(r1), "=r"(r2), "=r"(r3) : "r"(addr));
}

__device__ __forceinline__ void mma16816(float* c, const uint32_t* a, const uint32_t* b) {
    asm volatile("mma.sync.aligned.m16n8k16.row.col.f32.bf16.bf16.f32 "
                 "{%0,%1,%2,%3}, {%4,%5,%6,%7}, {%8,%9}, {%0,%1,%2,%3};"
                 : "+f"(c[0]), "+f"(c[1]), "+f"(c[2]), "+f"(c[3])
                 : "r"(a[0]), "r"(a[1]), "r"(a[2]), "r"(a[3]), "r"(b[0]), "r"(b[1]));
}

__device__ __forceinline__ void cpa16(uint32_t dst, const void* src) {
    asm volatile("cp.async.cg.shared.global [%0], [%1], 16;" :: "r"(dst), "l"(src));
}
#define CP_COMMIT() asm volatile("cp.async.commit_group;" ::: "memory")
#define CP_WAIT0()  asm volatile("cp.async.wait_group 0;" ::: "memory")

// ---------------- helpers ----------------
__device__ __forceinline__ float block_sum_256(float v, float* red) {
    int t = threadIdx.x;
    red[t] = v;
    __syncthreads();
#pragma unroll
    for (int s = 128; s > 0; s >>= 1) {
        if (t < s) red[t] += red[t + s];
        __syncthreads();
    }
    float r = red[0];
    __syncthreads();
    return r;
}

// ---------------- K0: transpose + bf16 split of X: [N,D] fp32 -> [D,N] hi/lo ----------------
__global__ __launch_bounds__(256) void bsplit_kernel(
    const float* __restrict__ X, __nv_bfloat16* __restrict__ hi, __nv_bfloat16* __restrict__ lo)
{
    __shared__ float tile[64][68];
    const int j0 = blockIdx.x * 64;
    const int d0 = blockIdx.y * 64;
    const int tid = threadIdx.x;
#pragma unroll
    for (int t = 0; t < 4; t++) {
        int idx = tid + 256 * t;
        int jj = idx >> 4, c4 = (idx & 15) * 4;
        float4 v = *(const float4*)&X[(size_t)(j0 + jj) * DD + d0 + c4];
        tile[jj][c4 + 0] = v.x; tile[jj][c4 + 1] = v.y;
        tile[jj][c4 + 2] = v.z; tile[jj][c4 + 3] = v.w;
    }
    __syncthreads();
#pragma unroll
    for (int t = 0; t < 4; t++) {
        int idx = tid + 256 * t;
        int dd = idx >> 4, q = (idx & 15) * 4;
        __nv_bfloat16 h[4], l[4];
#pragma unroll
        for (int k = 0; k < 4; k++) {
            float v = tile[q + k][dd];
            h[k] = __float2bfloat16(v);
            l[k] = __float2bfloat16(v - __bfloat162float(h[k]));
        }
        size_t o = (size_t)(d0 + dd) * NN + j0 + q;
        *(__nv_bfloat162*)&hi[o]     = __halves2bfloat162(h[0], h[1]);
        *(__nv_bfloat162*)&hi[o + 2] = __halves2bfloat162(h[2], h[3]);
        *(__nv_bfloat162*)&lo[o]     = __halves2bfloat162(l[0], l[1]);
        *(__nv_bfloat162*)&lo[o + 2] = __halves2bfloat162(l[2], l[3]);
    }
}

// ---------------- K1/K2: per-row |x|, x^2, relu-sum (degree) ----------------
__global__ __launch_bounds__(256) void row_reduce_kernel(
    const float* __restrict__ inc, int L,
    float* __restrict__ rowabs, float* __restrict__ rowsq, float* __restrict__ deg)
{
    __shared__ float red[256];
    int i = blockIdx.x;
    const float* row = inc + (size_t)i * L;
    float sa = 0.f, ss = 0.f, sd = 0.f;
    for (int j = threadIdx.x; j < L; j += 256) {
        float v = __ldg(&row[j]);
        sa += fabsf(v);
        ss += v * v;
        sd += fmaxf(v, 0.f);
    }
    sa = block_sum_256(sa, red);
    ss = block_sum_256(ss, red);
    sd = block_sum_256(sd, red);
    if (threadIdx.x == 0) {
        rowabs[i] = sa;
        rowsq[i]  = ss;
        deg[i]    = sd + 1.0f;
    }
}

// ---------------- BIG: mma.sync bf16 fused incidence GEMM ----------------
// Per CTA (M=128 rows, N=128 D-cols):
//   D_raw  = M @ X            (bf16, loss path)
//   D_relu = relu(M) @ X      (2-term bf16 split: rhi*bhi + rhi*blo + rlo*bhi)
//   emb    = (D_relu + cur)/deg ;  sqpart = sum((master - D_raw)^2)
#define LDA 144
#define AVAR (128 * LDA)        // 18432 bytes per variant tile
#define ST_MHI 0
#define ST_RHI (1 * AVAR)
#define ST_RLO (2 * AVAR)
#define ST_BHI (3 * AVAR)
#define ST_BLO (4 * AVAR)
#define STAGE  (5 * AVAR)       // 92160
#define BIG_SMEM (2 * STAGE)    // 184320
#define NCH 64

__global__ __launch_bounds__(256, 1) void big_inc_mma_kernel(
    const float* __restrict__ inc_s, const float* __restrict__ inc_t,
    const __nv_bfloat16* __restrict__ bhi_s, const __nv_bfloat16* __restrict__ blo_s,
    const __nv_bfloat16* __restrict__ bhi_t, const __nv_bfloat16* __restrict__ blo_t,
    const float* __restrict__ cur,
    const float* __restrict__ master_s, const float* __restrict__ master_t,
    const float* __restrict__ deg_s, const float* __restrict__ deg_t,
    float* __restrict__ emb_s, float* __restrict__ emb_t,
    float* __restrict__ sqpart_s, float* __restrict__ sqpart_t)
{
    extern __shared__ char smem[];
    const int tid = threadIdx.x;
    const int wid = tid >> 5;
    const int lane = tid & 31;
    const int cb = blockIdx.x;          // 0..1 (128 D-cols each)
    const int rb = blockIdx.y;          // 0..31 (128 rows each)
    const bool spatial = (blockIdx.z == 0);

    const float* inc = spatial ? inc_s : inc_t;
    const __nv_bfloat16* bh = spatial ? bhi_s : bhi_t;
    const __nv_bfloat16* bl = spatial ? blo_s : blo_t;
    const float* master = spatial ? master_s : master_t;
    const float* deg    = spatial ? deg_s : deg_t;
    float* emb          = spatial ? emb_s : emb_t;
    float* sqpart       = spatial ? sqpart_s : sqpart_t;

    const uint32_t sb = smem_to_u32(smem);

    // A staging: thread -> row (0..127), k-half (0 or 32)
    const int arow = tid >> 1;
    const int kh = (tid & 1) * 32;
    const int ig_a = rb * 128 + arow;

    // warp tile: 32 (M) x 64 (N)
    const int warp_m = (wid & 3) * 32;
    const int warp_n = (wid >> 2) * 64;

    float craw[2][8][4] = {};
    float crel[2][8][4] = {};
    float av[32];

    // ---- A chunk load (global -> regs) ----
    auto load_a = [&](int ch) {
        const int jb = ch * 64 + kh;
        if (spatial) {
            const float* rp = inc + (size_t)ig_a * (NN - 1);
#pragma unroll
            for (int c = 0; c < 32; c++) {
                int j = jb + c;
                av[c] = (j == ig_a) ? 0.f : __ldg(&rp[j < ig_a ? j : j - 1]);
            }
        } else {
            const float* rp = inc + (size_t)ig_a * NN + jb;
#pragma unroll
            for (int c = 0; c < 32; c += 4) {
                float4 v = *(const float4*)&rp[c];
                av[c] = v.x; av[c + 1] = v.y; av[c + 2] = v.z; av[c + 3] = v.w;
            }
        }
    };

    // ---- A convert + STS (regs -> smem stage) ----
    auto store_a = [&](int stage_off) {
        char* pm = smem + stage_off + ST_MHI + arow * LDA + kh * 2;
        char* ph = smem + stage_off + ST_RHI + arow * LDA + kh * 2;
        char* pl = smem + stage_off + ST_RLO + arow * LDA + kh * 2;
#pragma unroll
        for (int c = 0; c < 32; c += 2) {
            float v0 = av[c], v1 = av[c + 1];
            __nv_bfloat16 m0 = __float2bfloat16(v0);
            __nv_bfloat16 m1 = __float2bfloat16(v1);
            float r0 = fmaxf(v0, 0.f), r1 = fmaxf(v1, 0.f);
            __nv_bfloat16 h0 = __float2bfloat16(r0);
            __nv_bfloat16 h1 = __float2bfloat16(r1);
            __nv_bfloat16 l0 = __float2bfloat16(r0 - __bfloat162float(h0));
            __nv_bfloat16 l1 = __float2bfloat16(r1 - __bfloat162float(h1));
            *(__nv_bfloat162*)(pm + c * 2) = __halves2bfloat162(m0, m1);
            *(__nv_bfloat162*)(ph + c * 2) = __halves2bfloat162(h0, h1);
            *(__nv_bfloat162*)(pl + c * 2) = __halves2bfloat162(l0, l1);
        }
    };

    // ---- B chunk copy (global bf16 -> smem, async) ----
    auto load_b = [&](int ch, int stage_off) {
#pragma unroll
        for (int i = 0; i < 8; i++) {
            int e = tid + 256 * i;           // 0..2047
            int var = e >> 10;               // 0: hi, 1: lo
            int rem = e & 1023;
            int n = rem >> 3;                // 0..127
            int k8 = rem & 7;                // 0..7 (8 bf16 = 16B each)
            const __nv_bfloat16* src =
                (var ? bl : bh) + (size_t)(cb * 128 + n) * NN + ch * 64 + k8 * 8;
            uint32_t dst = sb + stage_off + (var ? ST_BLO : ST_BHI) + n * LDA + k8 * 16;
            cpa16(dst, src);
        }
    };

    // ---- MMA over one 64-wide K chunk ----
    auto do_mma = [&](int stage_off) {
        const uint32_t stb = sb + stage_off;
        const int ar = warp_m + (lane & 15);
        const int br = (lane & 7) + ((lane >> 4) & 1) * 8;
#pragma unroll
        for (int ks = 0; ks < 4; ks++) {
            const int acol = ks * 32 + (lane >> 4) * 16;       // bytes
            const int bcol = ks * 32 + ((lane >> 3) & 1) * 16; // bytes
            uint32_t amhi[2][4], arhi[2][4], arlo[2][4];
#pragma unroll
            for (int mt = 0; mt < 2; mt++) {
                uint32_t ao = stb + (ar + mt * 16) * LDA + acol;
                ldsm4(amhi[mt][0], amhi[mt][1], amhi[mt][2], amhi[mt][3], ao + ST_MHI);
                ldsm4(arhi[mt][0], arhi[mt][1], arhi[mt][2], arhi[mt][3], ao + ST_RHI);
                ldsm4(arlo[mt][0], arlo[mt][1], arlo[mt][2], arlo[mt][3], ao + ST_RLO);
            }
            uint32_t bhiR[8][2], bloR[8][2];
#pragma unroll
            for (int p = 0; p < 4; p++) {
                uint32_t bo = stb + (warp_n + p * 16 + br) * LDA + bcol;
                uint32_t r0, r1, r2, r3;
                ldsm4(r0, r1, r2, r3, bo + ST_BHI);
                bhiR[p * 2][0] = r0; bhiR[p * 2][1] = r1;
                bhiR[p * 2 + 1][0] = r2; bhiR[p * 2 + 1][1] = r3;
                ldsm4(r0, r1, r2, r3, bo + ST_BLO);
                bloR[p * 2][0] = r0; bloR[p * 2][1] = r1;
                bloR[p * 2 + 1][0] = r2; bloR[p * 2 + 1][1] = r3;
            }
#pragma unroll
            for (int mt = 0; mt < 2; mt++)
#pragma unroll
                for (int nt = 0; nt < 8; nt++) {
                    mma16816(craw[mt][nt], amhi[mt], bhiR[nt]);
                    mma16816(crel[mt][nt], arhi[mt], bhiR[nt]);
                    mma16816(crel[mt][nt], arhi[mt], bloR[nt]);
                    mma16816(crel[mt][nt], arlo[mt], bhiR[nt]);
                }
        }
    };

    // ---- prologue ----
    load_a(0);
    load_b(0, 0);
    CP_COMMIT();
    store_a(0);

    // ---- main loop ----
    for (int ch = 0; ch < NCH; ch++) {
        const int so = (ch & 1) * STAGE;
        const int sn = ((ch & 1) ^ 1) * STAGE;
        CP_WAIT0();
        __syncthreads();
        const bool more = (ch + 1 < NCH);
        if (more) {
            load_a(ch + 1);
            load_b(ch + 1, sn);
            CP_COMMIT();
        }
        do_mma(so);
        if (more) store_a(sn);
    }

    // ---- epilogue ----
    __syncthreads();
    float sq = 0.f;
#pragma unroll
    for (int mt = 0; mt < 2; mt++) {
        const int m0 = rb * 128 + warp_m + mt * 16 + (lane >> 2);
#pragma unroll
        for (int half = 0; half < 2; half++) {
            const int m = m0 + half * 8;
            const float invd = 1.0f / __ldg(&deg[m]);
#pragma unroll
            for (int nt = 0; nt < 8; nt++) {
                const int n = cb * 128 + warp_n + nt * 8 + (lane & 3) * 2;
                const size_t off = (size_t)m * DD + n;
                float2 ms = *(const float2*)&master[off];
                float2 cv = *(const float2*)&cur[off];
                float r0 = craw[mt][nt][half * 2 + 0];
                float r1 = craw[mt][nt][half * 2 + 1];
                float e0 = crel[mt][nt][half * 2 + 0];
                float e1 = crel[mt][nt][half * 2 + 1];
                float d0 = ms.x - r0, d1 = ms.y - r1;
                sq = fmaf(d0, d0, fmaf(d1, d1, sq));
                float2 o;
                o.x = (e0 + cv.x) * invd;
                o.y = (e1 + cv.y) * invd;
                *(float2*)&emb[off] = o;
            }
        }
    }
    float tot = block_sum_256(sq, (float*)smem);
    if (tid == 0) sqpart[rb * 2 + cb] = tot;
}

// ---------------- small GEMM C = A[N,D] @ op(B[D,D]) (+bias, relu) ----------------
template<bool TRANSB, bool RELUBIAS>
__global__ __launch_bounds__(256, 2) void gemm256_kernel(
    const float* __restrict__ A, const float* __restrict__ B,
    const float* __restrict__ bias, float* __restrict__ C)
{
    const int row0 = blockIdx.y * 64;
    const int col0 = blockIdx.x * 64;
    const int tid = threadIdx.x;
    const int ty = tid >> 4, tx = tid & 15;

    __shared__ float As[16][64];
    __shared__ float Bs[16][64];

    float acc[4][4];
#pragma unroll
    for (int m = 0; m < 4; m++)
#pragma unroll
        for (int n = 0; n < 4; n++) acc[m][n] = 0.f;

    const int lr = tid >> 2, lk = (tid & 3) * 4;
    const int bk = tid >> 4, bn = (tid & 15) * 4;
    const int tn = tid >> 2, tkq = (tid & 3) * 4;

    for (int k0 = 0; k0 < DD; k0 += 16) {
        float4 a4 = *(const float4*)&A[(size_t)(row0 + lr) * DD + k0 + lk];
        As[lk + 0][lr] = a4.x; As[lk + 1][lr] = a4.y;
        As[lk + 2][lr] = a4.z; As[lk + 3][lr] = a4.w;
        if (!TRANSB) {
            *(float4*)&Bs[bk][bn] =
                *(const float4*)&B[(size_t)(k0 + bk) * DD + col0 + bn];
        } else {
            float4 w = *(const float4*)&B[(size_t)(col0 + tn) * DD + k0 + tkq];
            Bs[tkq + 0][tn] = w.x; Bs[tkq + 1][tn] = w.y;
            Bs[tkq + 2][tn] = w.z; Bs[tkq + 3][tn] = w.w;
        }
        __syncthreads();
#pragma unroll
        for (int k = 0; k < 16; k++) {
            float4 a = *(const float4*)&As[k][ty * 4];
            float4 b = *(const float4*)&Bs[k][tx * 4];
            float am[4] = {a.x, a.y, a.z, a.w};
            float bv[4] = {b.x, b.y, b.z, b.w};
#pragma unroll
            for (int m = 0; m < 4; m++)
#pragma unroll
                for (int n = 0; n < 4; n++)
                    acc[m][n] = fmaf(am[m], bv[n], acc[m][n]);
        }
        __syncthreads();
    }

#pragma unroll
    for (int m = 0; m < 4; m++) {
        int gi = row0 + ty * 4 + m;
        float4 o;
        float v0 = acc[m][0], v1 = acc[m][1], v2 = acc[m][2], v3 = acc[m][3];
        if (RELUBIAS) {
            int gj = col0 + tx * 4;
            v0 = fmaxf(v0 + __ldg(&bias[gj + 0]), 0.f);
            v1 = fmaxf(v1 + __ldg(&bias[gj + 1]), 0.f);
            v2 = fmaxf(v2 + __ldg(&bias[gj + 2]), 0.f);
            v3 = fmaxf(v3 + __ldg(&bias[gj + 3]), 0.f);
        }
        o.x = v0; o.y = v1; o.z = v2; o.w = v3;
        *(float4*)&C[(size_t)gi * DD + col0 + tx * 4] = o;
    }
}

// ---------------- attention + val ----------------
__global__ __launch_bounds__(256) void attn_val_kernel() {
    __shared__ float red[256];
    int i = blockIdx.x;
    int d = threadIdx.x;
    size_t idx = (size_t)i * DD + d;
    float nf = g_node_fea[idx];
    float sf = g_spa_fea[idx];
    float tf = g_tmp_fea[idx];
    float ds = block_sum_256(sf * nf, red);
    float dt = block_sum_256(tf * nf, red);
    float as = ds * 0.0625f;  // 1/sqrt(256)
    float at = dt * 0.0625f;
    g_val[idx] = as * sf + at * tf;
}

// ---------------- finalize loss ----------------
__global__ __launch_bounds__(256) void finalize_kernel(float* __restrict__ out, int out_size) {
    __shared__ float red[256];
    int t = threadIdx.x;
    float abs_s = 0.f, sq_s = 0.f, abs_t = 0.f, sq_t = 0.f;
    for (int i = t; i < NN; i += 256) {
        abs_s += g_rowabs_s[i];
        sq_s  += g_rowsq_s[i];
        abs_t += g_rowabs_t[i];
        sq_t  += g_rowsq_t[i];
    }
    float d_s = (t < 64) ? g_sqpart_s[t] : 0.f;
    float d_t = (t < 64) ? g_sqpart_t[t] : 0.f;
    abs_s = block_sum_256(abs_s, red);
    sq_s  = block_sum_256(sq_s,  red);
    abs_t = block_sum_256(abs_t, red);
    sq_t  = block_sum_256(sq_t,  red);
    d_s   = block_sum_256(d_s,   red);
    d_t   = block_sum_256(d_t,   red);
    float loss = 0.2f * sqrtf(d_s) + abs_s + 0.001f * sqrtf(sq_s)
               + 0.2f * sqrtf(d_t) + abs_t + 0.001f * sqrtf(sq_t);
    for (int idx = NN * DD + t; idx < out_size; idx += 256)
        out[idx] = loss;
}

// ---------------- launch ----------------
extern "C" void kernel_launch(void* const* d_in, const int* in_sizes, int n_in,
                              void* d_out, int out_size) {
    const float* cur           = (const float*)d_in[0];
    const float* pre           = (const float*)d_in[1];
    const float* r_proj_s      = (const float*)d_in[2];
    const float* inc_s         = (const float*)d_in[3];
    const float* r_proj_t      = (const float*)d_in[4];
    const float* inc_t         = (const float*)d_in[5];
    const float* node_proj     = (const float*)d_in[6];
    const float* spa_edge_proj = (const float*)d_in[7];
    const float* tmp_edge_proj = (const float*)d_in[8];
    const float* theta_w       = (const float*)d_in[9];
    const float* theta_b       = (const float*)d_in[10];
    float* out = (float*)d_out;

    float *p_spa_emb, *p_tmp_emb, *p_node_fea, *p_spa_fea, *p_tmp_fea, *p_val;
    float *p_master_s, *p_master_t;
    float *p_deg_s, *p_deg_t, *p_rowabs_s, *p_rowsq_s, *p_rowabs_t, *p_rowsq_t;
    float *p_sqpart_s, *p_sqpart_t;
    __nv_bfloat16 *p_bhi_s, *p_blo_s, *p_bhi_t, *p_blo_t;
    cudaGetSymbolAddress((void**)&p_spa_emb,  g_spa_emb);
    cudaGetSymbolAddress((void**)&p_tmp_emb,  g_tmp_emb);
    cudaGetSymbolAddress((void**)&p_node_fea, g_node_fea);
    cudaGetSymbolAddress((void**)&p_spa_fea,  g_spa_fea);
    cudaGetSymbolAddress((void**)&p_tmp_fea,  g_tmp_fea);
    cudaGetSymbolAddress((void**)&p_val,      g_val);
    cudaGetSymbolAddress((void**)&p_master_s, g_master_s);
    cudaGetSymbolAddress((void**)&p_master_t, g_master_t);
    cudaGetSymbolAddress((void**)&p_deg_s,    g_deg_s);
    cudaGetSymbolAddress((void**)&p_deg_t,    g_deg_t);
    cudaGetSymbolAddress((void**)&p_rowabs_s, g_rowabs_s);
    cudaGetSymbolAddress((void**)&p_rowsq_s,  g_rowsq_s);
    cudaGetSymbolAddress((void**)&p_rowabs_t, g_rowabs_t);
    cudaGetSymbolAddress((void**)&p_rowsq_t,  g_rowsq_t);
    cudaGetSymbolAddress((void**)&p_sqpart_s, g_sqpart_s);
    cudaGetSymbolAddress((void**)&p_sqpart_t, g_sqpart_t);
    cudaGetSymbolAddress((void**)&p_bhi_s,    g_bhi_s);
    cudaGetSymbolAddress((void**)&p_blo_s,    g_blo_s);
    cudaGetSymbolAddress((void**)&p_bhi_t,    g_bhi_t);
    cudaGetSymbolAddress((void**)&p_blo_t,    g_blo_t);

    static bool attr_set = false;
    if (!attr_set) {
        cudaFuncSetAttribute(big_inc_mma_kernel,
                             cudaFuncAttributeMaxDynamicSharedMemorySize, BIG_SMEM);
        attr_set = true;
    }

    dim3 grid(DD / 64, NN / 64); // (4, 64)

    // pre-split + transpose of X for the big GEMM B operand
    bsplit_kernel<<<dim3(NN / 64, DD / 64), 256>>>(cur, p_bhi_s, p_blo_s);
    bsplit_kernel<<<dim3(NN / 64, DD / 64), 256>>>(pre, p_bhi_t, p_blo_t);

    // row reductions (degrees + loss row sums)
    row_reduce_kernel<<<NN, 256>>>(inc_s, NN - 1, p_rowabs_s, p_rowsq_s, p_deg_s);
    row_reduce_kernel<<<NN, 256>>>(inc_t, NN,     p_rowabs_t, p_rowsq_t, p_deg_t);

    // masters: cur @ r_proj_{s,t}
    gemm256_kernel<false, false><<<grid, 256>>>(cur, r_proj_s, nullptr, p_master_s);
    gemm256_kernel<false, false><<<grid, 256>>>(cur, r_proj_t, nullptr, p_master_t);

    // BIG tensor-core fused incidence GEMMs (both matrices, one wave of 128 CTAs)
    big_inc_mma_kernel<<<dim3(2, 32, 2), 256, BIG_SMEM>>>(
        inc_s, inc_t, p_bhi_s, p_blo_s, p_bhi_t, p_blo_t, cur,
        p_master_s, p_master_t, p_deg_s, p_deg_t,
        p_spa_emb, p_tmp_emb, p_sqpart_s, p_sqpart_t);

    // feature projections
    gemm256_kernel<false, false><<<grid, 256>>>(cur,       node_proj,     nullptr, p_node_fea);
    gemm256_kernel<false, false><<<grid, 256>>>(p_spa_emb, spa_edge_proj, nullptr, p_spa_fea);
    gemm256_kernel<false, false><<<grid, 256>>>(p_tmp_emb, tmp_edge_proj, nullptr, p_tmp_fea);

    // attention + val
    attn_val_kernel<<<NN, 256>>>();

    // node_emb = relu(val @ theta_w^T + theta_b)  -> d_out[0 .. N*D)
    gemm256_kernel<true, true><<<grid, 256>>>(p_val, theta_w, theta_b, out);

    // loss scalar -> d_out[N*D ...]
    finalize_kernel<<<1, 256>>>(out, out_size);
}